// round 8
// baseline (speedup 1.0000x reference)
#include <cuda_runtime.h>
#include <math.h>

#define BB 2
#define NN 384
#define CC 1024
#define HREPN 256
#define GHID 256
#define NHEADS 4
#define TOPKK 8
#define MAXDEG 400

typedef unsigned long long ull;

// ---------------- scratch (device globals; no allocation allowed) ------------
__device__ __align__(16) float g_p1 [BB*NN*HREPN];
__device__ __align__(16) float g_p2 [BB*NN*HREPN];
__device__ __align__(16) float g_xw1[BB*NN*NHEADS*GHID];
__device__ float g_as1[BB*NN*NHEADS];
__device__ float g_ad1[BB*NN*NHEADS];
__device__ int   g_nbr[BB*NN*TOPKK];
__device__ int   g_srcl[BB*NN*MAXDEG];
__device__ int   g_deg [BB*NN];
__device__ float g_xw2[BB*NN*2];
__device__ float g_as2[BB*NN];
__device__ float g_ad2[BB*NN];

// ---------------- f32x2 helpers ----------------------------------------------
__device__ __forceinline__ void ffma2(ull &d, ull a, ull b) {
    asm("fma.rn.f32x2 %0, %1, %2, %0;" : "+l"(d) : "l"(a), "l"(b));
}
__device__ __forceinline__ ull fma2v(ull a, ull b, ull c) {
    ull r; asm("fma.rn.f32x2 %0, %1, %2, %3;" : "=l"(r) : "l"(a), "l"(b), "l"(c)); return r;
}
__device__ __forceinline__ ull add2v(ull a, ull b) {
    ull r; asm("add.rn.f32x2 %0, %1, %2;" : "=l"(r) : "l"(a), "l"(b)); return r;
}
__device__ __forceinline__ ull pack2(float lo, float hi) {
    ull r; asm("mov.b64 %0, {%1, %2};" : "=l"(r) : "f"(lo), "f"(hi)); return r;
}
__device__ __forceinline__ void unpack2(ull v, float &lo, float &hi) {
    asm("mov.b64 {%0, %1}, %2;" : "=f"(lo), "=f"(hi) : "l"(v));
}
__device__ __forceinline__ float lo2(ull v) { return __uint_as_float((unsigned)(v & 0xffffffffull)); }
__device__ __forceinline__ float hi2(ull v) { return __uint_as_float((unsigned)(v >> 32)); }

// ---------------- tf32 helpers -----------------------------------------------
__device__ __forceinline__ void tf32split(float v, unsigned &hi, unsigned &lo) {
    asm("cvt.rna.tf32.f32 %0, %1;" : "=r"(hi) : "f"(v));
    float rem = v - __uint_as_float(hi);
    asm("cvt.rna.tf32.f32 %0, %1;" : "=r"(lo) : "f"(rem));
}
__device__ __forceinline__ void mma_tf32(float* c, const unsigned* a, const unsigned* b) {
    asm volatile(
        "mma.sync.aligned.m16n8k8.row.col.f32.tf32.tf32.f32 "
        "{%0,%1,%2,%3}, {%4,%5,%6,%7}, {%8,%9}, {%0,%1,%2,%3};"
        : "+f"(c[0]), "+f"(c[1]), "+f"(c[2]), "+f"(c[3])
        : "r"(a[0]), "r"(a[1]), "r"(a[2]), "r"(a[3]), "r"(b[0]), "r"(b[1]));
}

// ===== GEMM dispatcher: blocks 0..95 p1/p2 fp32-exact | 96..191 xw1 3xTF32 ===
__global__ __launch_bounds__(256) void k_gemms(
    const float* __restrict__ feats,
    const float* __restrict__ fc1_w,
    const float* __restrict__ gat1_w,
    const float* __restrict__ boxes)
{
    __shared__ __align__(16) float sm[10816];   // 43.3KB union
    int tid = threadIdx.x;
    int bid = blockIdx.x;

    if (bid < 96) {
        // ---------------- p1/p2 exact fp32 path: 64x64 tile, K-split ---------
        int b = bid / 48; int r = bid % 48;
        int by = r / 8, bx = r % 8;
        int row0 = by*64, col0 = bx*64;
        const float* Bm; float* Cm; int dcol0;
        if (col0 < 256) { Bm = fc1_w;            Cm = g_p1 + b*NN*256; dcol0 = col0; }
        else            { Bm = fc1_w + 1024*256; Cm = g_p2 + b*NN*256; dcol0 = col0 - 256; }

        int khalf = tid >> 7, htid = tid & 127;
        float* As = sm + khalf*2560;           // [buf][64*20]
        float* Bs = sm + 5120 + khalf*2816;    // [buf][64*22]
        int tx = htid & 15, ty = htid >> 4;

        ull acc[8][4];
        #pragma unroll
        for (int rr = 0; rr < 8; rr++)
            #pragma unroll
            for (int j = 0; j < 4; j++) acc[rr][j] = 0ull;

        int arow = htid >> 1, aslot = htid & 1;
        int bc = htid & 63, bk2 = htid >> 6;
        int kbase = khalf * 512;
        const float* Ap = feats + b*NN*1024 + (row0 + arow)*1024 + kbase + aslot*8;
        const float* Bp = Bm + kbase*256 + dcol0 + bc;

        float4 pa0 = *(const float4*)Ap;
        float4 pa1 = *(const float4*)(Ap + 4);
        float pb[8];
        #pragma unroll
        for (int m = 0; m < 8; m++) pb[m] = Bp[(bk2*8 + m)*256];
        *(float4*)&As[arow*20 + aslot*8]     = pa0;
        *(float4*)&As[arow*20 + aslot*8 + 4] = pa1;
        #pragma unroll
        for (int m = 0; m < 8; m++) Bs[bc*22 + bk2*8 + m] = pb[m];
        __syncthreads();

        for (int t = 0; t < 32; t++) {
            int cur = t & 1, nxt = cur ^ 1;
            if (t < 31) {
                int k0 = (t + 1) * 16;
                pa0 = *(const float4*)(Ap + k0);
                pa1 = *(const float4*)(Ap + k0 + 4);
                #pragma unroll
                for (int m = 0; m < 8; m++) pb[m] = Bp[(k0 + bk2*8 + m)*256];
            }
            #pragma unroll
            for (int kp = 0; kp < 8; kp++) {
                ull av[8], bv[4];
                #pragma unroll
                for (int rr = 0; rr < 8; rr++)
                    av[rr] = *(const ull*)&As[cur*1280 + (ty + 8*rr)*20 + 2*kp];
                #pragma unroll
                for (int j = 0; j < 4; j++)
                    bv[j] = *(const ull*)&Bs[cur*1408 + (tx + 16*j)*22 + 2*kp];
                #pragma unroll
                for (int rr = 0; rr < 8; rr++)
                    #pragma unroll
                    for (int j = 0; j < 4; j++) ffma2(acc[rr][j], av[rr], bv[j]);
            }
            if (t < 31) {
                *(float4*)&As[nxt*1280 + arow*20 + aslot*8]     = pa0;
                *(float4*)&As[nxt*1280 + arow*20 + aslot*8 + 4] = pa1;
                #pragma unroll
                for (int m = 0; m < 8; m++) Bs[nxt*1408 + bc*22 + bk2*8 + m] = pb[m];
            }
            __syncthreads();
        }

        // combine K-halves via padded smem (aliases As region — dead now)
        float* comb = sm;
        if (khalf == 1) {
            #pragma unroll
            for (int rr = 0; rr < 8; rr++)
                #pragma unroll
                for (int j = 0; j < 4; j++)
                    comb[htid*33 + rr*4 + j] = lo2(acc[rr][j]) + hi2(acc[rr][j]);
        }
        __syncthreads();
        if (khalf == 0) {
            #pragma unroll
            for (int rr = 0; rr < 8; rr++) {
                int row = row0 + ty + 8*rr;
                #pragma unroll
                for (int j = 0; j < 4; j++) {
                    float s = (lo2(acc[rr][j]) + hi2(acc[rr][j])) + comb[htid*33 + rr*4 + j];
                    Cm[row*256 + dcol0 + tx + 16*j] = s;
                }
            }
        }
    } else {
        // ---------------- xw1 3xTF32 tensor path: 128x64 block tile ----------
        int idx = bid - 96;
        int b = idx / 48; int r = idx % 48;
        int by = r / 16, bx = r % 16;
        int row0 = by*128, col0 = bx*64;
        float* smA = sm;            // [buf][128*20]
        float* smB = sm + 5120;     // [buf][64*20]
        float* Wg4 = sm + 7680;     // [4][64]
        Wg4[tid] = gat1_w[(1024 + (tid >> 6))*1024 + col0 + (tid & 63)];

        float* Cm = g_xw1 + b*NN*1024;
        int arow = tid >> 1, aslot = tid & 1;
        int bc = tid & 63, bq = tid >> 6;          // k = bq*4 + m
        const float* Ap = feats + b*NN*1024 + (row0 + arow)*1024 + aslot*8;
        const float* Bp = gat1_w + col0 + bc;

        int warp = tid >> 5, lane = tid & 31;
        int g = lane >> 2, tg = lane & 3;
        int wm = warp & 3, wn = warp >> 2;          // warp tile 32x32 at (32wm, 32wn)

        float acc[2][4][4];
        #pragma unroll
        for (int i = 0; i < 2; i++)
            #pragma unroll
            for (int j = 0; j < 4; j++)
                #pragma unroll
                for (int c = 0; c < 4; c++) acc[i][j][c] = 0.f;

        float4 pa0 = *(const float4*)Ap;
        float4 pa1 = *(const float4*)(Ap + 4);
        float pb[4];
        #pragma unroll
        for (int m = 0; m < 4; m++) pb[m] = Bp[(bq*4 + m)*1024];
        *(float4*)&smA[arow*20 + aslot*8]     = pa0;
        *(float4*)&smA[arow*20 + aslot*8 + 4] = pa1;
        #pragma unroll
        for (int m = 0; m < 4; m++) smB[bc*20 + bq*4 + m] = pb[m];
        __syncthreads();

        for (int t = 0; t < 64; t++) {
            int cur = t & 1, nxt = cur ^ 1;
            if (t < 63) {
                int k0 = (t + 1) * 16;
                pa0 = *(const float4*)(Ap + k0);
                pa1 = *(const float4*)(Ap + k0 + 4);
                #pragma unroll
                for (int m = 0; m < 4; m++) pb[m] = Bp[(k0 + bq*4 + m)*1024];
            }
            #pragma unroll
            for (int ks8 = 0; ks8 < 2; ks8++) {
                int ks = ks8 * 8;
                const float* A0 = smA + cur*2560;
                const float* B0 = smB + cur*1280;
                float af[2][4], bf[4][2];
                #pragma unroll
                for (int i = 0; i < 2; i++) {
                    int rb = wm*32 + i*16;
                    af[i][0] = A0[(rb + g    )*20 + ks + tg    ];
                    af[i][1] = A0[(rb + 8 + g)*20 + ks + tg    ];
                    af[i][2] = A0[(rb + g    )*20 + ks + tg + 4];
                    af[i][3] = A0[(rb + 8 + g)*20 + ks + tg + 4];
                }
                #pragma unroll
                for (int j = 0; j < 4; j++) {
                    int cb = wn*32 + j*8 + g;
                    bf[j][0] = B0[cb*20 + ks + tg    ];
                    bf[j][1] = B0[cb*20 + ks + tg + 4];
                }
                unsigned ah[2][4], al[2][4], bh[4][2], bl[4][2];
                #pragma unroll
                for (int i = 0; i < 2; i++)
                    #pragma unroll
                    for (int c = 0; c < 4; c++) tf32split(af[i][c], ah[i][c], al[i][c]);
                #pragma unroll
                for (int j = 0; j < 4; j++)
                    #pragma unroll
                    for (int c = 0; c < 2; c++) tf32split(bf[j][c], bh[j][c], bl[j][c]);
                #pragma unroll
                for (int i = 0; i < 2; i++)
                    #pragma unroll
                    for (int j = 0; j < 4; j++) {
                        mma_tf32(acc[i][j], ah[i], bh[j]);
                        mma_tf32(acc[i][j], al[i], bh[j]);
                        mma_tf32(acc[i][j], ah[i], bl[j]);
                    }
            }
            if (t < 63) {
                *(float4*)&smA[nxt*2560 + arow*20 + aslot*8]     = pa0;
                *(float4*)&smA[nxt*2560 + arow*20 + aslot*8 + 4] = pa1;
                #pragma unroll
                for (int m = 0; m < 4; m++) smB[nxt*1280 + bc*20 + bq*4 + m] = pb[m];
            }
            __syncthreads();
        }

        // epilogue: geometry fold + store
        #pragma unroll
        for (int i = 0; i < 2; i++) {
            int R = row0 + wm*32 + i*16;
            int ra = R + g, rb = R + 8 + g;
            const float* bxa = boxes + (b*NN + ra)*4;
            const float* bxb = boxes + (b*NN + rb)*4;
            float ax0 = bxa[0]*(1.0f/800.0f), ay0 = bxa[1]*(1.0f/800.0f);
            float ax1 = bxa[2]*(1.0f/800.0f), ay1 = bxa[3]*(1.0f/800.0f);
            float ga0 = ax0, ga1 = ay0, ga2 = ax1 - ax0, ga3 = ay1 - ay0;
            float bx0 = bxb[0]*(1.0f/800.0f), by0v = bxb[1]*(1.0f/800.0f);
            float bx1 = bxb[2]*(1.0f/800.0f), by1v = bxb[3]*(1.0f/800.0f);
            float gb0 = bx0, gb1 = by0v, gb2 = bx1 - bx0, gb3 = by1v - by0v;
            #pragma unroll
            for (int j = 0; j < 4; j++) {
                int Cl = wn*32 + j*8 + 2*tg;
                int col = col0 + Cl;
                float w00 = Wg4[Cl],       w01 = Wg4[Cl+1];
                float w10 = Wg4[64+Cl],    w11 = Wg4[64+Cl+1];
                float w20 = Wg4[128+Cl],   w21 = Wg4[128+Cl+1];
                float w30 = Wg4[192+Cl],   w31 = Wg4[192+Cl+1];
                float v0 = acc[i][j][0];
                v0 = fmaf(ga0,w00,v0); v0 = fmaf(ga1,w10,v0); v0 = fmaf(ga2,w20,v0); v0 = fmaf(ga3,w30,v0);
                float v1 = acc[i][j][1];
                v1 = fmaf(ga0,w01,v1); v1 = fmaf(ga1,w11,v1); v1 = fmaf(ga2,w21,v1); v1 = fmaf(ga3,w31,v1);
                float v2 = acc[i][j][2];
                v2 = fmaf(gb0,w00,v2); v2 = fmaf(gb1,w10,v2); v2 = fmaf(gb2,w20,v2); v2 = fmaf(gb3,w30,v2);
                float v3 = acc[i][j][3];
                v3 = fmaf(gb0,w01,v3); v3 = fmaf(gb1,w11,v3); v3 = fmaf(gb2,w21,v3); v3 = fmaf(gb3,w31,v3);
                *(float2*)&Cm[ra*1024 + col] = make_float2(v0, v1);
                *(float2*)&Cm[rb*1024 + col] = make_float2(v2, v3);
            }
        }
    }
}

// ------- merged: relation scores + top-8 (blocks 0..191)  |  asad (192..575) -
__global__ __launch_bounds__(256) void k_rel_asad(
    const float* __restrict__ boxes,
    const float* __restrict__ fc1_w,
    const float* __restrict__ fc1_b,
    const float* __restrict__ fc2_w,
    const float* __restrict__ att_src,
    const float* __restrict__ att_dst)
{
    __shared__ float srow[4][NN];
    __shared__ float sbx[16];
    int bid = blockIdx.x;
    int tid = threadIdx.x, warp = tid >> 5, lane = tid & 31;

    if (bid >= 192) {
        int bn = (bid - 192)*2 + (tid >> 7);
        int h = (tid >> 5) & 3;
        const float* xw = g_xw1 + bn*1024 + h*256 + lane*8;
        float4 v0 = *(const float4*)xw;
        float4 v1 = *(const float4*)(xw + 4);
        const float* asr = att_src + h*256 + lane*8;
        const float* adr = att_dst + h*256 + lane*8;
        float4 s0 = *(const float4*)asr;
        float4 s1 = *(const float4*)(asr + 4);
        float4 d0 = *(const float4*)adr;
        float4 d1 = *(const float4*)(adr + 4);
        float ss = v0.x*s0.x + v0.y*s0.y + v0.z*s0.z + v0.w*s0.w
                 + v1.x*s1.x + v1.y*s1.y + v1.z*s1.z + v1.w*s1.w;
        float dd = v0.x*d0.x + v0.y*d0.y + v0.z*d0.z + v0.w*d0.w
                 + v1.x*d1.x + v1.y*d1.y + v1.z*d1.z + v1.w*d1.w;
        #pragma unroll
        for (int o = 16; o; o >>= 1) {
            ss += __shfl_down_sync(0xffffffffu, ss, o);
            dd += __shfl_down_sync(0xffffffffu, dd, o);
        }
        if (lane == 0) { g_as1[bn*4 + h] = ss; g_ad1[bn*4 + h] = dd; }
        return;
    }

    int b = bid / 96, igrp = bid % 96;
    int i0 = igrp * 4;

    if (tid < 16) sbx[tid] = boxes[(b*NN + i0 + (tid >> 2))*4 + (tid & 3)];

    ull wg2[4][4], sp1q[4][4];
    float w2lo[4], w2hi[4];
    #pragma unroll
    for (int p = 0; p < 4; p++) {
        int k0 = lane + 64*p, k1 = k0 + 32;
        w2lo[p] = fc2_w[k0];
        w2hi[p] = fc2_w[k1];
        #pragma unroll
        for (int d = 0; d < 4; d++)
            wg2[d][p] = pack2(fc1_w[(2048+d)*256 + k0], fc1_w[(2048+d)*256 + k1]);
        float b0 = fc1_b[k0], b1 = fc1_b[k1];
        #pragma unroll
        for (int q = 0; q < 4; q++) {
            const float* p1r = g_p1 + (b*NN + i0 + q)*256;
            sp1q[q][p] = pack2(p1r[k0] + b0, p1r[k1] + b1);
        }
    }
    __syncthreads();

    const float* p2b = g_p2 + b*NN*256;
    const float* bxb = boxes + b*NN*4;

    for (int j = warp; j < NN; j += 8) {
        float4 bj = *(const float4*)&bxb[j*4];
        ull p2v[4];
        #pragma unroll
        for (int p = 0; p < 4; p++) {
            int k0 = lane + 64*p;
            p2v[p] = pack2(p2b[j*256 + k0], p2b[j*256 + k0 + 32]);
        }
        #pragma unroll
        for (int q = 0; q < 4; q++) {
            float d0 = fabsf(sbx[q*4+0] - bj.x);
            float d1 = fabsf(sbx[q*4+1] - bj.y);
            float d2 = fabsf(sbx[q*4+2] - bj.z);
            float d3 = fabsf(sbx[q*4+3] - bj.w);
            ull a0 = pack2(d0, d0), a1 = pack2(d1, d1);
            ull a2 = pack2(d2, d2), a3 = pack2(d3, d3);
            float sum = 0.f;
            #pragma unroll
            for (int p = 0; p < 4; p++) {
                ull t = add2v(sp1q[q][p], p2v[p]);
                t = fma2v(a0, wg2[0][p], t);
                t = fma2v(a1, wg2[1][p], t);
                t = fma2v(a2, wg2[2][p], t);
                t = fma2v(a3, wg2[3][p], t);
                float tl, th;
                unpack2(t, tl, th);
                tl = fmaxf(tl, 0.f);
                th = fmaxf(th, 0.f);
                sum = fmaf(tl, w2lo[p], sum);
                sum = fmaf(th, w2hi[p], sum);
            }
            #pragma unroll
            for (int o = 16; o; o >>= 1) sum += __shfl_down_sync(0xffffffffu, sum, o);
            if (lane == 0)
                srow[q][j] = sum - ((j == i0 + q) ? 1e6f : 0.f);
        }
    }
    __syncthreads();

    if (warp < 4) {
        int q = warp, i = i0 + q;
        for (int sel = 0; sel < TOPKK; sel++) {
            float bv = -3.4e38f; int bi = 1 << 30;
            for (int j = lane; j < NN; j += 32) {
                float v = srow[q][j];
                if (v > bv || (v == bv && j < bi)) { bv = v; bi = j; }
            }
            #pragma unroll
            for (int o = 16; o; o >>= 1) {
                float ov = __shfl_xor_sync(0xffffffffu, bv, o);
                int   oi = __shfl_xor_sync(0xffffffffu, bi, o);
                if (ov > bv || (ov == bv && oi < bi)) { bv = ov; bi = oi; }
            }
            if (lane == 0) {
                g_nbr[(b*NN + i)*TOPKK + sel] = bi;
                srow[q][bi] = -3.4e38f;
            }
            __syncwarp();
        }
    }
}

// -------- GAT1: fused edge-build + softmax + float4 aggregate + xw2 ----------
__global__ __launch_bounds__(256) void k_gat1(
    const float* __restrict__ gat1_b,
    const float* __restrict__ gat2_w,
    const float* __restrict__ att_src2,
    const float* __restrict__ att_dst2)
{
    int bn = blockIdx.x; int b = bn / NN, tt = bn % NN;
    __shared__ int   ssrc[MAXDEG];
    __shared__ float sal[NHEADS][MAXDEG];
    __shared__ float sas1[NN*4];
    __shared__ int   scnt[256];
    __shared__ float red[8][2];
    __shared__ int   sdeg;
    int tid = threadIdx.x;

    #pragma unroll
    for (int it = 0; it < 6; it++)
        sas1[tid + it*256] = g_as1[b*NN*4 + tid + it*256];

    const int* nb = g_nbr + b*NN*TOPKK;
    int myc0 = 0, myc1 = 0;
    int ia = 2*tid, ib = 2*tid + 1;
    if (tid < 192) {
        #pragma unroll
        for (int k = 0; k < TOPKK; k++) {
            myc0 += (nb[ia*TOPKK + k] == tt);
            myc1 += (nb[ib*TOPKK + k] == tt);
        }
    }
    int tot = myc0 + myc1;
    scnt[tid] = tot;
    __syncthreads();
    for (int s = 1; s < 256; s <<= 1) {
        int v = (tid >= s) ? scnt[tid - s] : 0;
        __syncthreads();
        scnt[tid] += v;
        __syncthreads();
    }
    int off = scnt[tid] - tot;
    int* dst = g_srcl + bn*MAXDEG;
    if (tid < 192) {
        if (myc0) {
            #pragma unroll
            for (int k = 0; k < TOPKK; k++)
                if (nb[ia*TOPKK + k] == tt) { ssrc[off] = ia; dst[off] = ia; off++; }
        }
        if (myc1) {
            #pragma unroll
            for (int k = 0; k < TOPKK; k++)
                if (nb[ib*TOPKK + k] == tt) { ssrc[off] = ib; dst[off] = ib; off++; }
        }
    }
    if (tid == 255) {
        int total = scnt[255];
        ssrc[total] = tt;
        dst[total] = tt;
        g_deg[bn] = total + 1;
        sdeg = total + 1;
    }
    __syncthreads();
    int deg = sdeg;

    int warp = tid >> 5, lane = tid & 31;
    if (warp < NHEADS) {
        int h = warp;
        float adv = g_ad1[bn*4 + h];
        float m = -3.4e38f;
        for (int s = lane; s < deg; s += 32) {
            float e = sas1[ssrc[s]*4 + h] + adv;
            e = (e >= 0.f) ? e : 0.2f*e;
            sal[h][s] = e;
            m = fmaxf(m, e);
        }
        #pragma unroll
        for (int o = 16; o; o >>= 1) m = fmaxf(m, __shfl_xor_sync(0xffffffffu, m, o));
        float sum = 0.f;
        for (int s = lane; s < deg; s += 32) {
            float ex = expf(sal[h][s] - m);
            sal[h][s] = ex;
            sum += ex;
        }
        #pragma unroll
        for (int o = 16; o; o >>= 1) sum += __shfl_xor_sync(0xffffffffu, sum, o);
        float inv = 1.f / fmaxf(sum, 1e-16f);
        for (int s = lane; s < deg; s += 32) sal[h][s] *= inv;
    }
    __syncthreads();

    const float* xwb = g_xw1 + b*NN*1024;
    const float* salh = sal[tid >> 6];
    float4 acc0 = make_float4(0.f, 0.f, 0.f, 0.f);
    float4 acc1 = make_float4(0.f, 0.f, 0.f, 0.f);
    int col4 = tid * 4;
    int s = 0;
    for (; s + 1 < deg; s += 2) {
        float4 v0 = *(const float4*)&xwb[ssrc[s  ]*1024 + col4];
        float4 v1 = *(const float4*)&xwb[ssrc[s+1]*1024 + col4];
        float a0 = salh[s], a1 = salh[s+1];
        acc0.x = fmaf(v0.x, a0, acc0.x); acc0.y = fmaf(v0.y, a0, acc0.y);
        acc0.z = fmaf(v0.z, a0, acc0.z); acc0.w = fmaf(v0.w, a0, acc0.w);
        acc1.x = fmaf(v1.x, a1, acc1.x); acc1.y = fmaf(v1.y, a1, acc1.y);
        acc1.z = fmaf(v1.z, a1, acc1.z); acc1.w = fmaf(v1.w, a1, acc1.w);
    }
    if (s < deg) {
        float4 v0 = *(const float4*)&xwb[ssrc[s]*1024 + col4];
        float a0 = salh[s];
        acc0.x = fmaf(v0.x, a0, acc0.x); acc0.y = fmaf(v0.y, a0, acc0.y);
        acc0.z = fmaf(v0.z, a0, acc0.z); acc0.w = fmaf(v0.w, a0, acc0.w);
    }
    float4 bia = *(const float4*)&gat1_b[col4];
    float4 oh;
    oh.x = fmaxf(acc0.x + acc1.x + bia.x, 0.f);
    oh.y = fmaxf(acc0.y + acc1.y + bia.y, 0.f);
    oh.z = fmaxf(acc0.z + acc1.z + bia.z, 0.f);
    oh.w = fmaxf(acc0.w + acc1.w + bia.w, 0.f);

    float4 w0 = *(const float4*)&gat2_w[col4*2];
    float4 w1 = *(const float4*)&gat2_w[col4*2 + 4];
    float c0 = oh.x*w0.x + oh.y*w0.z + oh.z*w1.x + oh.w*w1.z;
    float c1 = oh.x*w0.y + oh.y*w0.w + oh.z*w1.y + oh.w*w1.w;
    #pragma unroll
    for (int o = 16; o; o >>= 1) {
        c0 += __shfl_down_sync(0xffffffffu, c0, o);
        c1 += __shfl_down_sync(0xffffffffu, c1, o);
    }
    if (lane == 0) { red[warp][0] = c0; red[warp][1] = c1; }
    __syncthreads();
    if (tid == 0) {
        float s0 = 0.f, s1 = 0.f;
        #pragma unroll
        for (int w = 0; w < 8; w++) { s0 += red[w][0]; s1 += red[w][1]; }
        g_xw2[bn*2 + 0] = s0;
        g_xw2[bn*2 + 1] = s1;
        g_as2[bn] = s0*att_src2[0] + s1*att_src2[1];
        g_ad2[bn] = s0*att_dst2[0] + s1*att_dst2[1];
    }
}

// ------- GAT layer 2: 8 nodes/block, batch as2/xw2 preloaded into smem -------
__global__ __launch_bounds__(256) void k_gat2(const float* __restrict__ gat2_b,
                                              float* __restrict__ out)
{
    __shared__ float s_as2[NN];
    __shared__ float s_xw2[NN*2];
    __shared__ float sal[8][MAXDEG];
    __shared__ int   ssrc[8][MAXDEG];
    int tid = threadIdx.x;
    int warp = tid >> 5, lane = tid & 31;
    int n0 = blockIdx.x * 8;
    int b = n0 / NN;

    for (int i = tid; i < NN; i += 256)   s_as2[i] = g_as2[b*NN + i];
    for (int i = tid; i < NN*2; i += 256) s_xw2[i] = g_xw2[b*NN*2 + i];
    __syncthreads();

    int bn = n0 + warp;
    int deg = g_deg[bn];
    for (int s = lane; s < deg; s += 32) ssrc[warp][s] = g_srcl[bn*MAXDEG + s];
    __syncwarp();
    float adv = g_ad2[bn];
    float m = -3.4e38f;
    for (int s = lane; s < deg; s += 32) {
        float e = s_as2[ssrc[warp][s]] + adv;
        e = (e >= 0.f) ? e : 0.2f*e;
        sal[warp][s] = e;
        m = fmaxf(m, e);
    }
    #pragma unroll
    for (int o = 16; o; o >>= 1) m = fmaxf(m, __shfl_xor_sync(0xffffffffu, m, o));
    float sum = 0.f;
    for (int s = lane; s < deg; s += 32) {
        float ex = expf(sal[warp][s] - m);
        sal[warp][s] = ex;
        sum += ex;
    }
    #pragma unroll
    for (int o = 16; o; o >>= 1) sum += __shfl_xor_sync(0xffffffffu, sum, o);
    float inv = 1.f / fmaxf(sum, 1e-16f);
    __syncwarp();
    float a0 = 0.f, a1 = 0.f;
    for (int s = lane; s < deg; s += 32) {
        float w = sal[warp][s] * inv;
        int sc = ssrc[warp][s];
        a0 = fmaf(s_xw2[sc*2 + 0], w, a0);
        a1 = fmaf(s_xw2[sc*2 + 1], w, a1);
    }
    #pragma unroll
    for (int o = 16; o; o >>= 1) {
        a0 += __shfl_down_sync(0xffffffffu, a0, o);
        a1 += __shfl_down_sync(0xffffffffu, a1, o);
    }
    if (lane == 0) {
        out[bn*2 + 0] = a0 + gat2_b[0];
        out[bn*2 + 1] = a1 + gat2_b[1];
    }
}

// ---------------- launch ------------------------------------------------------
extern "C" void kernel_launch(void* const* d_in, const int* in_sizes, int n_in,
                              void* d_out, int out_size)
{
    const float* feats   = (const float*)d_in[0];
    const float* boxes   = (const float*)d_in[1];
    const float* fc1_w   = (const float*)d_in[2];
    const float* fc1_b   = (const float*)d_in[3];
    const float* fc2_w   = (const float*)d_in[4];
    // d_in[5] = fc2_b : constant shift, irrelevant for top-k
    const float* gat1_w  = (const float*)d_in[6];
    const float* g1as    = (const float*)d_in[7];
    const float* g1ad    = (const float*)d_in[8];
    const float* gat1_b  = (const float*)d_in[9];
    const float* gat2_w  = (const float*)d_in[10];
    const float* g2as    = (const float*)d_in[11];
    const float* g2ad    = (const float*)d_in[12];
    const float* gat2_b  = (const float*)d_in[13];
    float* out = (float*)d_out;

    k_gemms   <<<192, 256>>>(feats, fc1_w, gat1_w, boxes);
    k_rel_asad<<<192 + 384, 256>>>(boxes, fc1_w, fc1_b, fc2_w, g1as, g1ad);
    k_gat1    <<<BB*NN, 256>>>(gat1_b, gat2_w, g2as, g2ad);
    k_gat2    <<<96, 256>>>(gat2_b, out);
    (void)in_sizes; (void)n_in; (void)out_size;
}